// round 14
// baseline (speedup 1.0000x reference)
#include <cuda_runtime.h>
#include <cuda_bf16.h>
#include <cstdint>

#define SEQ   2048
#define BATCH 64
#define HID   256
#define G4    1024
#define NCTA  128
#define NGRP  16
#define HS_ELEMS (BATCH*SEQ*HID)

#define VT_LD  132
#define HS_LD  260
#define RED_LD 516
#define SM_VT  0
#define SM_H   (256*VT_LD)                    // 33792
#define SM_RED (SM_H + 4*HS_LD)               // +1040 = 34832
#define SM_TOT (SM_RED + 8*RED_LD)            // +4128 = 38960 floats (~156 KB)

__device__ float    g_xU[(size_t)SEQ * BATCH * G4];
__device__ float    g_hbuf[2][BATCH * HID];
__device__ unsigned g_flag[NGRP][8 * 32];     // one 128B line per (group, cg)
__device__ unsigned g_icount[NGRP];
__device__ unsigned g_igen[NGRP];

__device__ __forceinline__ float4 ldcg4(const float4* p) {
    float4 v;
    asm volatile("ld.global.cg.v4.f32 {%0,%1,%2,%3}, [%4];"
                 : "=f"(v.x), "=f"(v.y), "=f"(v.z), "=f"(v.w) : "l"(p));
    return v;
}
__device__ __forceinline__ unsigned ld_acquire_u32(const unsigned* p) {
    unsigned v;
    asm volatile("ld.acquire.gpu.global.u32 %0, [%1];" : "=r"(v) : "l"(p) : "memory");
    return v;
}
__device__ __forceinline__ void st_release_u32(unsigned* p, unsigned v) {
    asm volatile("st.release.gpu.global.u32 [%0], %1;" :: "l"(p), "r"(v) : "memory");
}
__device__ __forceinline__ void st_relaxed_u32(unsigned* p, unsigned v) {
    asm volatile("st.relaxed.gpu.global.u32 [%0], %1;" :: "l"(p), "r"(v) : "memory");
}
__device__ __forceinline__ void stcg_f32(float* p, float v) {
    asm volatile("st.global.cg.f32 [%0], %1;" :: "l"(p), "f"(v) : "memory");
}
// Blackwell packed fp32 FMA: d = a*b + d  (two independent fp32 lanes, .rn)
__device__ __forceinline__ void fma2(unsigned long long& d, unsigned long long a,
                                     unsigned long long b) {
    asm("fma.rn.f32x2 %0, %1, %2, %0;" : "+l"(d) : "l"(a), "l"(b));
}
__device__ __forceinline__ unsigned long long pack2(float x) {
    unsigned long long r;
    asm("mov.b64 %0, {%1, %1};" : "=l"(r) : "f"(x));
    return r;
}

__device__ __forceinline__ float sigf(float x)     { return 1.f / (1.f + __expf(-x)); }
__device__ __forceinline__ float tanhfast(float x) { return 1.f - 2.f / (__expf(2.f * x) + 1.f); }

// ---- kernel 1: xU GEMM (proven). grid (16, 2048), 256 thr ----
__global__ void __launch_bounds__(256) xu_gemm(
    const float* __restrict__ x,
    const float* __restrict__ U0, const float* __restrict__ U1,
    const float* __restrict__ U2, const float* __restrict__ U3,
    const float* __restrict__ B0, const float* __restrict__ B1,
    const float* __restrict__ B2, const float* __restrict__ B3)
{
    __shared__ float As[16][68];
    __shared__ float Bs[16][64];

    const int t     = blockIdx.y;
    const int nb    = blockIdx.x;
    const int gate  = nb >> 2;
    const int ucol0 = (nb & 3) * 64;
    const float* U  = (gate == 0) ? U0 : (gate == 1) ? U1 : (gate == 2) ? U2 : U3;
    const float* Bb = (gate == 0) ? B0 : (gate == 1) ? B1 : (gate == 2) ? B2 : B3;

    const int tid  = threadIdx.x;
    const int ty   = tid >> 4;
    const int tx   = tid & 15;
    const int bRow = tid >> 2;
    const int kq   = (tid & 3) << 2;
    const int kRow = tid >> 4;
    const int n4   = (tid & 15) << 2;

    const float* xrow = x + ((size_t)bRow * SEQ + t) * 256;
    float acc[4][4] = {};

    for (int kb = 0; kb < 256; kb += 16) {
        float4 xa = *(const float4*)(xrow + kb + kq);
        As[kq + 0][bRow] = xa.x;
        As[kq + 1][bRow] = xa.y;
        As[kq + 2][bRow] = xa.z;
        As[kq + 3][bRow] = xa.w;
        *(float4*)&Bs[kRow][n4] = *(const float4*)(U + (size_t)(kb + kRow) * 256 + ucol0 + n4);
        __syncthreads();
#pragma unroll
        for (int kk = 0; kk < 16; ++kk) {
            float4 a = *(float4*)&As[kk][ty * 4];
            float4 b = *(float4*)&Bs[kk][tx * 4];
            float av[4] = {a.x, a.y, a.z, a.w};
            float bv[4] = {b.x, b.y, b.z, b.w};
#pragma unroll
            for (int i = 0; i < 4; ++i)
#pragma unroll
                for (int j = 0; j < 4; ++j)
                    acc[i][j] += av[i] * bv[j];
        }
        __syncthreads();
    }

    float4 bv4 = *(const float4*)(Bb + ucol0 + tx * 4);
    float bb[4] = {bv4.x, bv4.y, bv4.z, bv4.w};
#pragma unroll
    for (int i = 0; i < 4; ++i) {
        int row = t * BATCH + ty * 4 + i;
        float4 o;
        o.x = acc[i][0] + bb[0];
        o.y = acc[i][1] + bb[1];
        o.z = acc[i][2] + bb[2];
        o.w = acc[i][3] + bb[3];
        *(float4*)&g_xU[(size_t)row * G4 + nb * 64 + tx * 4] = o;
    }
}

// ---- kernel 2: recurrence. 128 CTAs = 16 groups x 8; warp-autonomous steps ----
__global__ void __launch_bounds__(256, 1) lstm_rec(
    const float* __restrict__ V0, const float* __restrict__ V1,
    const float* __restrict__ V2, const float* __restrict__ V3,
    float* __restrict__ out, int write_final)
{
    extern __shared__ float sm[];
    float* vt  = sm + SM_VT;     // [256][VT_LD]  vt[k][c], c = g*32+ul
    float* h_s = sm + SM_H;      // [4][HS_LD]   (per-warp exclusive k-slices)
    float* red = sm + SM_RED;    // [8][RED_LD]

    const int tid = threadIdx.x;
    const int ci  = blockIdx.x;
    const int bg  = ci >> 3;
    const int cg  = ci & 7;
    const int b0  = bg * 4;
    const int u0  = cg * 32;

    // V slice
    for (int i = tid; i < 256 * 128; i += 256) {
        int k = i >> 7, c = i & 127;
        int g = c >> 5, ul = c & 31;
        const float* Vg = (g == 0) ? V0 : (g == 1) ? V1 : (g == 2) ? V2 : V3;
        vt[k * VT_LD + c] = Vg[k * 256 + u0 + ul];
    }

    // --- replay-safe init: reset own flag, zero h buffer 0, then group barrier ---
    if (tid == 0) st_relaxed_u32(&g_flag[bg][cg * 32], 0u);
    if (cg == 0)
        for (int i = tid; i < 4 * 256; i += 256)
            g_hbuf[0][b0 * 256 + i] = 0.f;
    __threadfence();
    __syncthreads();
    if (tid == 0) {
        unsigned target = atomicAdd(&g_igen[bg], 0u) + 1u;
        unsigned a = atomicAdd(&g_icount[bg], 1u);
        if (a == 7u) {
            atomicExch(&g_icount[bg], 0u);
            __threadfence();
            atomicAdd(&g_igen[bg], 1u);
        } else {
            while (atomicAdd(&g_igen[bg], 0u) != target) {}
        }
        __threadfence();
    }
    __syncthreads();

    // mappings
    const int ks    = tid >> 5;        // warp id: K slice [ks*32, ks*32+32)
    const int lane  = tid & 31;
    const int c0    = lane * 4;        // 4 gate-cols (2 f32x2 pairs)
    const int kbase = ks * 32;
    const int sb    = lane >> 3;       // staging batch 0..3
    const int skq   = (lane & 7) << 2; // staging k-quad
    const int eb = tid >> 5;           // epilogue (tid<128): batch eb, unit ul
    const int ul = tid & 31;
    float c_state = 0.f;

    const float* vbase = vt + kbase * VT_LD + c0;
    float* hstage = &h_s[sb * HS_LD + kbase + skq];
    const float4* hsrc0 = (const float4*)(g_hbuf[0] + (b0 + sb) * 256 + kbase + skq);
    const float4* hsrc1 = (const float4*)(g_hbuf[1] + (b0 + sb) * 256 + kbase + skq);

    for (int t = 0; t < SEQ; ++t) {
        const int pr = t & 1, pw = pr ^ 1;

        // per-warp wait: lanes 0-7 poll the 8 group flags for step t
        if (t > 0) {
            if (lane < 8) {
                const unsigned* fp = &g_flag[bg][lane * 32];
                while (ld_acquire_u32(fp) < (unsigned)t) {}
            }
            __syncwarp();
        }

        // xU prefetch (warps 0-3 only; consumed in epilogue)
        float xu0 = 0.f, xu1 = 0.f, xu2 = 0.f, xu3 = 0.f;
        if (tid < 128) {
            const float* xp = g_xU + ((size_t)t * BATCH + b0 + eb) * G4 + u0 + ul;
            xu0 = __ldg(xp); xu1 = __ldg(xp + 256); xu2 = __ldg(xp + 512); xu3 = __ldg(xp + 768);
        }

        // warp-local staging: this warp's 32-k slice of all 4 batches (512B)
        {
            float4 v = ldcg4(pr ? hsrc1 : hsrc0);
            *(float4*)hstage = v;
            __syncwarp();
        }

        // dot over k in [kbase, kbase+32), packed f32x2 over column pairs
        unsigned long long acc2[4][2] = {};
#pragma unroll
        for (int kk = 0; kk < 32; kk += 4) {
            float4 h0v = *(const float4*)&h_s[0 * HS_LD + kbase + kk];
            float4 h1v = *(const float4*)&h_s[1 * HS_LD + kbase + kk];
            float4 h2v = *(const float4*)&h_s[2 * HS_LD + kbase + kk];
            float4 h3v = *(const float4*)&h_s[3 * HS_LD + kbase + kk];
            float ha[4][4] = {{h0v.x, h0v.y, h0v.z, h0v.w},
                              {h1v.x, h1v.y, h1v.z, h1v.w},
                              {h2v.x, h2v.y, h2v.z, h2v.w},
                              {h3v.x, h3v.y, h3v.z, h3v.w}};
            const float* vp = vbase + kk * VT_LD;
#pragma unroll
            for (int k = 0; k < 4; ++k) {
                ulonglong2 vv = *(const ulonglong2*)(vp + k * VT_LD);
#pragma unroll
                for (int b = 0; b < 4; ++b) {
                    unsigned long long hp = pack2(ha[b][k]);
                    fma2(acc2[b][0], hp, vv.x);
                    fma2(acc2[b][1], hp, vv.y);
                }
            }
        }

        // K partials (bit layout identical to float4 {c0,c1,c2,c3})
        {
            float* rp = red + ks * RED_LD + c0;
            *(ulonglong2*)&rp[0 * 128] = make_ulonglong2(acc2[0][0], acc2[0][1]);
            *(ulonglong2*)&rp[1 * 128] = make_ulonglong2(acc2[1][0], acc2[1][1]);
            *(ulonglong2*)&rp[2 * 128] = make_ulonglong2(acc2[2][0], acc2[2][1]);
            *(ulonglong2*)&rp[3 * 128] = make_ulonglong2(acc2[3][0], acc2[3][1]);
        }
        __syncthreads();

        // epilogue: 128 threads, one (batch, unit) each
        if (tid < 128) {
            float z0 = xu0, z1 = xu1, z2 = xu2, z3 = xu3;
            int base = eb * 128 + ul;
#pragma unroll
            for (int s = 0; s < 8; ++s) {
                const float* rr = red + s * RED_LD + base;
                z0 += rr[0]; z1 += rr[32]; z2 += rr[64]; z3 += rr[96];
            }
            float ig = sigf(z0), fg = sigf(z1), og = sigf(z2), gg = tanhfast(z3);
            c_state = fg * c_state + ig * gg;
            float h = og * tanhfast(c_state);
            int b = b0 + eb, u = u0 + ul;
            stcg_f32(&g_hbuf[pw][b * 256 + u], h);
            out[((size_t)b * SEQ + t) * HID + u] = h;
            if (write_final && t == SEQ - 1) {
                out[(size_t)HS_ELEMS + b * HID + u]               = h;
                out[(size_t)HS_ELEMS + BATCH * HID + b * HID + u] = c_state;
            }
        }
        __syncthreads();
        // release publishes all pre-barrier writes (CTA barrier gives causality)
        if (tid == 0) st_release_u32(&g_flag[bg][cg * 32], (unsigned)(t + 1));
    }
}

extern "C" void kernel_launch(void* const* d_in, const int* in_sizes, int n_in,
                              void* d_out, int out_size) {
    const float* x  = (const float*)d_in[0];
    const float* Ui = (const float*)d_in[1];
    const float* Vi = (const float*)d_in[2];
    const float* bi = (const float*)d_in[3];
    const float* Uf = (const float*)d_in[4];
    const float* Vf = (const float*)d_in[5];
    const float* bf = (const float*)d_in[6];
    const float* Uo = (const float*)d_in[7];
    const float* Vo = (const float*)d_in[8];
    const float* bo = (const float*)d_in[9];
    const float* Uc = (const float*)d_in[10];
    const float* Vc = (const float*)d_in[11];
    const float* bc = (const float*)d_in[12];
    float* out = (float*)d_out;

    static int smem_set = 0;
    if (!smem_set) {
        cudaFuncSetAttribute(lstm_rec, cudaFuncAttributeMaxDynamicSharedMemorySize,
                             SM_TOT * (int)sizeof(float));
        smem_set = 1;
    }

    dim3 ggrid(16, SEQ);
    xu_gemm<<<ggrid, 256>>>(x, Ui, Uf, Uo, Uc, bi, bf, bo, bc);

    int write_final = (out_size >= HS_ELEMS + 2 * BATCH * HID) ? 1 : 0;
    lstm_rec<<<NCTA, 256, SM_TOT * (int)sizeof(float)>>>(Vi, Vf, Vo, Vc, out, write_final);
}

// round 15
// speedup vs baseline: 1.1899x; 1.1899x over previous
#include <cuda_runtime.h>
#include <cuda_bf16.h>
#include <cstdint>

#define SEQ   2048
#define BATCH 64
#define HID   256
#define G4    1024
#define NCTA  128
#define NGRP  16
#define HS_ELEMS (BATCH*SEQ*HID)

#define VT_LD  132
#define HS_LD  260
#define RED_LD 516
#define SM_VT  0
#define SM_H   (256*VT_LD)                    // 33792
#define SM_RED (SM_H + 4*HS_LD)               // +1040 = 34832
#define SM_TOT (SM_RED + 8*RED_LD)            // +4128 = 38960 floats (~156 KB)

__device__ float    g_xU[(size_t)SEQ * BATCH * G4];
__device__ float    g_hbuf[2][BATCH * HID];
__device__ unsigned g_flag[NGRP][8 * 32];     // one 128B line per (group, cg)
__device__ unsigned g_icount[NGRP];
__device__ unsigned g_igen[NGRP];

__device__ __forceinline__ float4 ldcg4(const float4* p) {
    float4 v;
    asm volatile("ld.global.cg.v4.f32 {%0,%1,%2,%3}, [%4];"
                 : "=f"(v.x), "=f"(v.y), "=f"(v.z), "=f"(v.w) : "l"(p));
    return v;
}
__device__ __forceinline__ unsigned ld_acquire_u32(const unsigned* p) {
    unsigned v;
    asm volatile("ld.acquire.gpu.global.u32 %0, [%1];" : "=r"(v) : "l"(p) : "memory");
    return v;
}
__device__ __forceinline__ void st_release_u32(unsigned* p, unsigned v) {
    asm volatile("st.release.gpu.global.u32 [%0], %1;" :: "l"(p), "r"(v) : "memory");
}
__device__ __forceinline__ void st_relaxed_u32(unsigned* p, unsigned v) {
    asm volatile("st.relaxed.gpu.global.u32 [%0], %1;" :: "l"(p), "r"(v) : "memory");
}
__device__ __forceinline__ void stcg_f32(float* p, float v) {
    asm volatile("st.global.cg.f32 [%0], %1;" :: "l"(p), "f"(v) : "memory");
}

__device__ __forceinline__ float sigf(float x)     { return 1.f / (1.f + __expf(-x)); }
__device__ __forceinline__ float tanhfast(float x) { return 1.f - 2.f / (__expf(2.f * x) + 1.f); }

// ---- kernel 1: xU GEMM (proven). grid (16, 2048), 256 thr ----
__global__ void __launch_bounds__(256) xu_gemm(
    const float* __restrict__ x,
    const float* __restrict__ U0, const float* __restrict__ U1,
    const float* __restrict__ U2, const float* __restrict__ U3,
    const float* __restrict__ B0, const float* __restrict__ B1,
    const float* __restrict__ B2, const float* __restrict__ B3)
{
    __shared__ float As[16][68];
    __shared__ float Bs[16][64];

    const int t     = blockIdx.y;
    const int nb    = blockIdx.x;
    const int gate  = nb >> 2;
    const int ucol0 = (nb & 3) * 64;
    const float* U  = (gate == 0) ? U0 : (gate == 1) ? U1 : (gate == 2) ? U2 : U3;
    const float* Bb = (gate == 0) ? B0 : (gate == 1) ? B1 : (gate == 2) ? B2 : B3;

    const int tid  = threadIdx.x;
    const int ty   = tid >> 4;
    const int tx   = tid & 15;
    const int bRow = tid >> 2;
    const int kq   = (tid & 3) << 2;
    const int kRow = tid >> 4;
    const int n4   = (tid & 15) << 2;

    const float* xrow = x + ((size_t)bRow * SEQ + t) * 256;
    float acc[4][4] = {};

    for (int kb = 0; kb < 256; kb += 16) {
        float4 xa = *(const float4*)(xrow + kb + kq);
        As[kq + 0][bRow] = xa.x;
        As[kq + 1][bRow] = xa.y;
        As[kq + 2][bRow] = xa.z;
        As[kq + 3][bRow] = xa.w;
        *(float4*)&Bs[kRow][n4] = *(const float4*)(U + (size_t)(kb + kRow) * 256 + ucol0 + n4);
        __syncthreads();
#pragma unroll
        for (int kk = 0; kk < 16; ++kk) {
            float4 a = *(float4*)&As[kk][ty * 4];
            float4 b = *(float4*)&Bs[kk][tx * 4];
            float av[4] = {a.x, a.y, a.z, a.w};
            float bv[4] = {b.x, b.y, b.z, b.w};
#pragma unroll
            for (int i = 0; i < 4; ++i)
#pragma unroll
                for (int j = 0; j < 4; ++j)
                    acc[i][j] += av[i] * bv[j];
        }
        __syncthreads();
    }

    float4 bv4 = *(const float4*)(Bb + ucol0 + tx * 4);
    float bb[4] = {bv4.x, bv4.y, bv4.z, bv4.w};
#pragma unroll
    for (int i = 0; i < 4; ++i) {
        int row = t * BATCH + ty * 4 + i;
        float4 o;
        o.x = acc[i][0] + bb[0];
        o.y = acc[i][1] + bb[1];
        o.z = acc[i][2] + bb[2];
        o.w = acc[i][3] + bb[3];
        *(float4*)&g_xU[(size_t)row * G4 + nb * 64 + tx * 4] = o;
    }
}

// ---- kernel 2: recurrence. 16 groups x 8 CTAs; per-warp pairwise sync ----
__global__ void __launch_bounds__(256, 1) lstm_rec(
    const float* __restrict__ V0, const float* __restrict__ V1,
    const float* __restrict__ V2, const float* __restrict__ V3,
    float* __restrict__ out, int write_final)
{
    extern __shared__ float sm[];
    float* vt  = sm + SM_VT;     // [256][VT_LD]  vt[k][c], c = g*32+ul
    float* h_s = sm + SM_H;      // [4][HS_LD]  (warp ks owns k-cols [32ks,32ks+32))
    float* red = sm + SM_RED;    // [8][RED_LD]

    const int tid = threadIdx.x;
    const int ci  = blockIdx.x;
    const int bg  = ci >> 3;
    const int cg  = ci & 7;
    const int b0  = bg * 4;
    const int u0  = cg * 32;

    // V slice
    for (int i = tid; i < 256 * 128; i += 256) {
        int k = i >> 7, c = i & 127;
        int g = c >> 5, ul = c & 31;
        const float* Vg = (g == 0) ? V0 : (g == 1) ? V1 : (g == 2) ? V2 : V3;
        vt[k * VT_LD + c] = Vg[k * 256 + u0 + ul];
    }

    // --- replay-safe init: reset own flag, zero h buffer 0, then group barrier ---
    if (tid == 0) st_relaxed_u32(&g_flag[bg][cg * 32], 0u);
    if (cg == 0)
        for (int i = tid; i < 4 * 256; i += 256)
            g_hbuf[0][b0 * 256 + i] = 0.f;
    __threadfence();
    __syncthreads();
    if (tid == 0) {
        unsigned target = atomicAdd(&g_igen[bg], 0u) + 1u;
        unsigned a = atomicAdd(&g_icount[bg], 1u);
        if (a == 7u) {
            atomicExch(&g_icount[bg], 0u);
            __threadfence();
            atomicAdd(&g_igen[bg], 1u);
        } else {
            while (atomicAdd(&g_igen[bg], 0u) != target) {}
        }
        __threadfence();
    }
    __syncthreads();

    // mappings
    const int ks    = tid >> 5;        // warp id; consumes h[32ks, 32ks+32) from peer cg==ks
    const int lane  = tid & 31;
    const int c0    = lane * 4;
    const int kbase = ks * 32;
    const int sb    = lane >> 3;       // staging batch 0..3
    const int skq   = (lane & 7) << 2; // staging k-quad
    const int eb = tid >> 5;           // epilogue (tid<128): batch eb, unit ul
    const int ul = tid & 31;
    float c_state = 0.f;

    const float* vbase = vt + kbase * VT_LD + c0;
    float* hstage = &h_s[sb * HS_LD + kbase + skq];
    const float4* hsrc0 = (const float4*)(g_hbuf[0] + (b0 + sb) * 256 + kbase + skq);
    const float4* hsrc1 = (const float4*)(g_hbuf[1] + (b0 + sb) * 256 + kbase + skq);
    const unsigned* myflag = &g_flag[bg][ks * 32];   // producer of this warp's h slice

    for (int t = 0; t < SEQ; ++t) {
        const int pr = t & 1, pw = pr ^ 1;

        // xU prefetch first — independent of peers, hidden under wait+dot
        float xu0 = 0.f, xu1 = 0.f, xu2 = 0.f, xu3 = 0.f;
        if (tid < 128) {
            const float* xp = g_xU + ((size_t)t * BATCH + b0 + eb) * G4 + u0 + ul;
            xu0 = __ldg(xp); xu1 = __ldg(xp + 256); xu2 = __ldg(xp + 512); xu3 = __ldg(xp + 768);
        }

        // pairwise wait: whole warp acquires ONE flag (its producer's)
        if (t > 0) {
            while (ld_acquire_u32(myflag) < (unsigned)t) {}
        }

        // warp-local staging: this warp's 32-k slice of all 4 batches (512B)
        {
            float4 v = ldcg4(pr ? hsrc1 : hsrc0);
            *(float4*)hstage = v;
        }
        __syncwarp();

        // dot over k in [kbase, kbase+32)  (R13 scalar form — proven fast)
        float acc[4][4] = {};
#pragma unroll
        for (int kk = 0; kk < 32; kk += 4) {
            float4 h0v = *(const float4*)&h_s[0 * HS_LD + kbase + kk];
            float4 h1v = *(const float4*)&h_s[1 * HS_LD + kbase + kk];
            float4 h2v = *(const float4*)&h_s[2 * HS_LD + kbase + kk];
            float4 h3v = *(const float4*)&h_s[3 * HS_LD + kbase + kk];
            const float* vp = vbase + kk * VT_LD;
            float4 va = *(const float4*)(vp);
            float4 vb = *(const float4*)(vp + VT_LD);
            float4 vc = *(const float4*)(vp + 2 * VT_LD);
            float4 vd = *(const float4*)(vp + 3 * VT_LD);
#define MAC4(hb, b) \
            acc[b][0] += hb.x*va.x + hb.y*vb.x + hb.z*vc.x + hb.w*vd.x; \
            acc[b][1] += hb.x*va.y + hb.y*vb.y + hb.z*vc.y + hb.w*vd.y; \
            acc[b][2] += hb.x*va.z + hb.y*vb.z + hb.z*vc.z + hb.w*vd.z; \
            acc[b][3] += hb.x*va.w + hb.y*vb.w + hb.z*vc.w + hb.w*vd.w;
            MAC4(h0v, 0) MAC4(h1v, 1) MAC4(h2v, 2) MAC4(h3v, 3)
#undef MAC4
        }

        // K partials
        {
            float* rp = red + ks * RED_LD + c0;
            *(float4*)&rp[0 * 128] = make_float4(acc[0][0], acc[0][1], acc[0][2], acc[0][3]);
            *(float4*)&rp[1 * 128] = make_float4(acc[1][0], acc[1][1], acc[1][2], acc[1][3]);
            *(float4*)&rp[2 * 128] = make_float4(acc[2][0], acc[2][1], acc[2][2], acc[2][3]);
            *(float4*)&rp[3 * 128] = make_float4(acc[3][0], acc[3][1], acc[3][2], acc[3][3]);
        }
        __syncthreads();

        // epilogue: 128 threads, one (batch, unit) each
        if (tid < 128) {
            float z0 = xu0, z1 = xu1, z2 = xu2, z3 = xu3;
            int base = eb * 128 + ul;
#pragma unroll
            for (int s = 0; s < 8; ++s) {
                const float* rr = red + s * RED_LD + base;
                z0 += rr[0]; z1 += rr[32]; z2 += rr[64]; z3 += rr[96];
            }
            float ig = sigf(z0), fg = sigf(z1), og = sigf(z2), gg = tanhfast(z3);
            c_state = fg * c_state + ig * gg;
            float h = og * tanhfast(c_state);
            int b = b0 + eb, u = u0 + ul;
            stcg_f32(&g_hbuf[pw][b * 256 + u], h);
            out[((size_t)b * SEQ + t) * HID + u] = h;
            if (write_final && t == SEQ - 1) {
                out[(size_t)HS_ELEMS + b * HID + u]               = h;
                out[(size_t)HS_ELEMS + BATCH * HID + b * HID + u] = c_state;
            }
        }
        __syncthreads();
        // release publishes all pre-barrier writes (CTA barrier gives causality)
        if (tid == 0) st_release_u32(&g_flag[bg][cg * 32], (unsigned)(t + 1));
    }
}

extern "C" void kernel_launch(void* const* d_in, const int* in_sizes, int n_in,
                              void* d_out, int out_size) {
    const float* x  = (const float*)d_in[0];
    const float* Ui = (const float*)d_in[1];
    const float* Vi = (const float*)d_in[2];
    const float* bi = (const float*)d_in[3];
    const float* Uf = (const float*)d_in[4];
    const float* Vf = (const float*)d_in[5];
    const float* bf = (const float*)d_in[6];
    const float* Uo = (const float*)d_in[7];
    const float* Vo = (const float*)d_in[8];
    const float* bo = (const float*)d_in[9];
    const float* Uc = (const float*)d_in[10];
    const float* Vc = (const float*)d_in[11];
    const float* bc = (const float*)d_in[12];
    float* out = (float*)d_out;

    static int smem_set = 0;
    if (!smem_set) {
        cudaFuncSetAttribute(lstm_rec, cudaFuncAttributeMaxDynamicSharedMemorySize,
                             SM_TOT * (int)sizeof(float));
        smem_set = 1;
    }

    dim3 ggrid(16, SEQ);
    xu_gemm<<<ggrid, 256>>>(x, Ui, Uf, Uo, Uc, bi, bf, bo, bc);

    int write_final = (out_size >= HS_ELEMS + 2 * BATCH * HID) ? 1 : 0;
    lstm_rec<<<NCTA, 256, SM_TOT * (int)sizeof(float)>>>(Vi, Vf, Vo, Vc, out, write_final);
}

// round 16
// speedup vs baseline: 1.4373x; 1.2080x over previous
#include <cuda_runtime.h>
#include <cuda_bf16.h>
#include <cstdint>

#define SEQ   2048
#define BATCH 64
#define HID   256
#define G4    1024
#define NCTA  128
#define NGRP  16
#define HS_ELEMS (BATCH*SEQ*HID)

#define VT_LD  132
#define HS_LD  260
#define RED_LD 516
#define SM_VT  0
#define SM_H   (256*VT_LD)                    // 33792
#define SM_RED (SM_H + 4*HS_LD)               // +1040 = 34832
#define SM_TOT (SM_RED + 2*8*RED_LD)          // +8256 = 43088 floats (~172 KB)

__device__ float              g_xU[(size_t)SEQ * BATCH * G4];
__device__ unsigned long long g_htag[2][BATCH * HID];   // {tag:u32, f32 bits}
__device__ unsigned           g_icount[NGRP];
__device__ unsigned           g_igen[NGRP];

__device__ __forceinline__ unsigned long long ld_relaxed_u64(const unsigned long long* p) {
    unsigned long long v;
    asm volatile("ld.relaxed.gpu.global.u64 %0, [%1];" : "=l"(v) : "l"(p) : "memory");
    return v;
}
__device__ __forceinline__ void st_relaxed_u64(unsigned long long* p, unsigned long long v) {
    asm volatile("st.relaxed.gpu.global.u64 [%0], %1;" :: "l"(p), "l"(v) : "memory");
}
__device__ __forceinline__ unsigned long long pack_ht(float h, unsigned tag) {
    return ((unsigned long long)tag << 32) | (unsigned long long)__float_as_uint(h);
}
__device__ __forceinline__ unsigned tag_of(unsigned long long v) { return (unsigned)(v >> 32); }
__device__ __forceinline__ float    val_of(unsigned long long v) { return __uint_as_float((unsigned)v); }

// f32x2 helpers (GEMM only — throughput-bound, packing amortizes)
__device__ __forceinline__ void fma2(unsigned long long& d, unsigned long long a,
                                     unsigned long long b) {
    asm("fma.rn.f32x2 %0, %1, %2, %0;" : "+l"(d) : "l"(a), "l"(b));
}
__device__ __forceinline__ unsigned long long pack2(float x) {
    unsigned long long r;
    asm("mov.b64 %0, {%1, %1};" : "=l"(r) : "f"(x));
    return r;
}
__device__ __forceinline__ float2 unpack2(unsigned long long v) {
    float2 f;
    asm("mov.b64 {%0, %1}, %2;" : "=f"(f.x), "=f"(f.y) : "l"(v));
    return f;
}

__device__ __forceinline__ float sigf(float x)     { return 1.f / (1.f + __expf(-x)); }
__device__ __forceinline__ float tanhfast(float x) { return 1.f - 2.f / (__expf(2.f * x) + 1.f); }

// ---- kernel 1: xU GEMM with packed f32x2 FMA. grid (16, 2048), 256 thr ----
__global__ void __launch_bounds__(256) xu_gemm(
    const float* __restrict__ x,
    const float* __restrict__ U0, const float* __restrict__ U1,
    const float* __restrict__ U2, const float* __restrict__ U3,
    const float* __restrict__ B0, const float* __restrict__ B1,
    const float* __restrict__ B2, const float* __restrict__ B3)
{
    __shared__ float As[16][68];
    __shared__ float Bs[16][64];

    const int t     = blockIdx.y;
    const int nb    = blockIdx.x;
    const int gate  = nb >> 2;
    const int ucol0 = (nb & 3) * 64;
    const float* U  = (gate == 0) ? U0 : (gate == 1) ? U1 : (gate == 2) ? U2 : U3;
    const float* Bb = (gate == 0) ? B0 : (gate == 1) ? B1 : (gate == 2) ? B2 : B3;

    const int tid  = threadIdx.x;
    const int ty   = tid >> 4;
    const int tx   = tid & 15;
    const int bRow = tid >> 2;
    const int kq   = (tid & 3) << 2;
    const int kRow = tid >> 4;
    const int n4   = (tid & 15) << 2;

    const float* xrow = x + ((size_t)bRow * SEQ + t) * 256;
    unsigned long long acc2[4][2] = {};   // acc2[i][p] = {col 2p, col 2p+1}

    for (int kb = 0; kb < 256; kb += 16) {
        float4 xa = *(const float4*)(xrow + kb + kq);
        As[kq + 0][bRow] = xa.x;
        As[kq + 1][bRow] = xa.y;
        As[kq + 2][bRow] = xa.z;
        As[kq + 3][bRow] = xa.w;
        *(float4*)&Bs[kRow][n4] = *(const float4*)(U + (size_t)(kb + kRow) * 256 + ucol0 + n4);
        __syncthreads();
#pragma unroll
        for (int kk = 0; kk < 16; ++kk) {
            float4 a = *(float4*)&As[kk][ty * 4];
            ulonglong2 bp = *(const ulonglong2*)&Bs[kk][tx * 4];
            unsigned long long a0 = pack2(a.x), a1 = pack2(a.y),
                               a2 = pack2(a.z), a3 = pack2(a.w);
            fma2(acc2[0][0], a0, bp.x); fma2(acc2[0][1], a0, bp.y);
            fma2(acc2[1][0], a1, bp.x); fma2(acc2[1][1], a1, bp.y);
            fma2(acc2[2][0], a2, bp.x); fma2(acc2[2][1], a2, bp.y);
            fma2(acc2[3][0], a3, bp.x); fma2(acc2[3][1], a3, bp.y);
        }
        __syncthreads();
    }

    float4 bv4 = *(const float4*)(Bb + ucol0 + tx * 4);
#pragma unroll
    for (int i = 0; i < 4; ++i) {
        int row = t * BATCH + ty * 4 + i;
        float2 lo = unpack2(acc2[i][0]), hi = unpack2(acc2[i][1]);
        float4 o;
        o.x = lo.x + bv4.x;
        o.y = lo.y + bv4.y;
        o.z = hi.x + bv4.z;
        o.w = hi.y + bv4.w;
        *(float4*)&g_xU[(size_t)row * G4 + nb * 64 + tx * 4] = o;
    }
}

// ---- kernel 2: recurrence. 16 groups x 8 CTAs; tagged-h sync, 1 barrier/step ----
__global__ void __launch_bounds__(256, 1) lstm_rec(
    const float* __restrict__ V0, const float* __restrict__ V1,
    const float* __restrict__ V2, const float* __restrict__ V3,
    float* __restrict__ out, int write_final)
{
    extern __shared__ float sm[];
    float* vt  = sm + SM_VT;     // [256][VT_LD]  vt[k][c], c = g*32+ul
    float* h_s = sm + SM_H;      // [4][HS_LD]   per-warp exclusive k-slices
    float* red = sm + SM_RED;    // [2][8][RED_LD] parity double-buffered partials

    const int tid = threadIdx.x;
    const int ci  = blockIdx.x;
    const int bg  = ci >> 3;
    const int cg  = ci & 7;
    const int b0  = bg * 4;
    const int u0  = cg * 32;

    // V slice
    for (int i = tid; i < 256 * 128; i += 256) {
        int k = i >> 7, c = i & 127;
        int g = c >> 5, ul2 = c & 31;
        const float* Vg = (g == 0) ? V0 : (g == 1) ? V1 : (g == 2) ? V2 : V3;
        vt[k * VT_LD + c] = Vg[k * 256 + u0 + ul2];
    }

    // --- replay-safe init: reset our tagged slots (both parities), group barrier ---
    {
        // 2 parities x 4 batches x 32 units = 256 slots, one per thread
        int par = tid >> 7, b = (tid >> 5) & 3, uu = tid & 31;
        st_relaxed_u64(&g_htag[par][(b0 + b) * 256 + u0 + uu], 0ull);
    }
    __threadfence();
    __syncthreads();
    if (tid == 0) {
        unsigned target = atomicAdd(&g_igen[bg], 0u) + 1u;
        unsigned a = atomicAdd(&g_icount[bg], 1u);
        if (a == 7u) {
            atomicExch(&g_icount[bg], 0u);
            __threadfence();
            atomicAdd(&g_igen[bg], 1u);
        } else {
            while (atomicAdd(&g_igen[bg], 0u) != target) {}
        }
        __threadfence();
    }
    __syncthreads();

    // mappings
    const int ks    = tid >> 5;        // warp id; consumes h[32ks, 32ks+32)
    const int lane  = tid & 31;
    const int c0    = lane * 4;
    const int kbase = ks * 32;
    const int sb    = lane >> 3;       // staging batch 0..3
    const int skq   = (lane & 7) << 2; // staging k-quad
    const int eb = tid >> 5;           // epilogue (tid<128): batch eb, unit ul
    const int ul = tid & 31;
    float c_state = 0.f;

    const float* vbase = vt + kbase * VT_LD + c0;
    float* hstage = &h_s[sb * HS_LD + kbase + skq];
    const unsigned long long* hsrc0 = &g_htag[0][(b0 + sb) * 256 + kbase + skq];
    const unsigned long long* hsrc1 = &g_htag[1][(b0 + sb) * 256 + kbase + skq];
    unsigned long long* hdst = (tid < 128) ? &g_htag[0][(b0 + eb) * 256 + u0 + ul] : 0;

    for (int t = 0; t < SEQ; ++t) {
        const int pr = t & 1, pw = pr ^ 1;

        // xU prefetch — independent of peers, hidden under poll+dot
        float xu0 = 0.f, xu1 = 0.f, xu2 = 0.f, xu3 = 0.f;
        if (tid < 128) {
            const float* xp = g_xU + ((size_t)t * BATCH + b0 + eb) * G4 + u0 + ul;
            xu0 = __ldg(xp); xu1 = __ldg(xp + 256); xu2 = __ldg(xp + 512); xu3 = __ldg(xp + 768);
        }

        // tagged poll + stage: flag and payload in one word
        if (t == 0) {
            *(float4*)hstage = make_float4(0.f, 0.f, 0.f, 0.f);
        } else {
            const unsigned long long* hp = pr ? hsrc1 : hsrc0;
            unsigned long long v0, v1, v2, v3;
            const unsigned wanted = (unsigned)t;
            do {
                v0 = ld_relaxed_u64(hp + 0);
                v1 = ld_relaxed_u64(hp + 1);
                v2 = ld_relaxed_u64(hp + 2);
                v3 = ld_relaxed_u64(hp + 3);
            } while (tag_of(v0) < wanted || tag_of(v1) < wanted ||
                     tag_of(v2) < wanted || tag_of(v3) < wanted);
            *(float4*)hstage = make_float4(val_of(v0), val_of(v1), val_of(v2), val_of(v3));
        }
        __syncwarp();

        // dot over k in [kbase, kbase+32)  (proven scalar form)
        float acc[4][4] = {};
#pragma unroll
        for (int kk = 0; kk < 32; kk += 4) {
            float4 h0v = *(const float4*)&h_s[0 * HS_LD + kbase + kk];
            float4 h1v = *(const float4*)&h_s[1 * HS_LD + kbase + kk];
            float4 h2v = *(const float4*)&h_s[2 * HS_LD + kbase + kk];
            float4 h3v = *(const float4*)&h_s[3 * HS_LD + kbase + kk];
            const float* vp = vbase + kk * VT_LD;
            float4 va = *(const float4*)(vp);
            float4 vb = *(const float4*)(vp + VT_LD);
            float4 vc = *(const float4*)(vp + 2 * VT_LD);
            float4 vd = *(const float4*)(vp + 3 * VT_LD);
#define MAC4(hb, b) \
            acc[b][0] += hb.x*va.x + hb.y*vb.x + hb.z*vc.x + hb.w*vd.x; \
            acc[b][1] += hb.x*va.y + hb.y*vb.y + hb.z*vc.y + hb.w*vd.y; \
            acc[b][2] += hb.x*va.z + hb.y*vb.z + hb.z*vc.z + hb.w*vd.z; \
            acc[b][3] += hb.x*va.w + hb.y*vb.w + hb.z*vc.w + hb.w*vd.w;
            MAC4(h0v, 0) MAC4(h1v, 1) MAC4(h2v, 2) MAC4(h3v, 3)
#undef MAC4
        }

        // K partials into parity buffer
        {
            float* rp = red + (pr * 8 + ks) * RED_LD + c0;
            *(float4*)&rp[0 * 128] = make_float4(acc[0][0], acc[0][1], acc[0][2], acc[0][3]);
            *(float4*)&rp[1 * 128] = make_float4(acc[1][0], acc[1][1], acc[1][2], acc[1][3]);
            *(float4*)&rp[2 * 128] = make_float4(acc[2][0], acc[2][1], acc[2][2], acc[2][3]);
            *(float4*)&rp[3 * 128] = make_float4(acc[3][0], acc[3][1], acc[3][2], acc[3][3]);
        }
        __syncthreads();   // the ONLY CTA barrier per step

        // epilogue: 128 threads, one (batch, unit) each
        if (tid < 128) {
            float z0 = xu0, z1 = xu1, z2 = xu2, z3 = xu3;
            int base = eb * 128 + ul;
            const float* rpar = red + pr * 8 * RED_LD;
#pragma unroll
            for (int s = 0; s < 8; ++s) {
                const float* rr = rpar + s * RED_LD + base;
                z0 += rr[0]; z1 += rr[32]; z2 += rr[64]; z3 += rr[96];
            }
            float ig = sigf(z0), fg = sigf(z1), og = sigf(z2), gg = tanhfast(z3);
            c_state = fg * c_state + ig * gg;
            float h = og * tanhfast(c_state);

            // publish tagged h (tag = t+1) into parity-pw buffer
            st_relaxed_u64(hdst + (size_t)pw * BATCH * HID, pack_ht(h, (unsigned)(t + 1)));

            int b = b0 + eb, u = u0 + ul;
            out[((size_t)b * SEQ + t) * HID + u] = h;
            if (write_final && t == SEQ - 1) {
                out[(size_t)HS_ELEMS + b * HID + u]               = h;
                out[(size_t)HS_ELEMS + BATCH * HID + b * HID + u] = c_state;
            }
        }
        // no second barrier: red is parity double-buffered, tags self-synchronize
    }
}

extern "C" void kernel_launch(void* const* d_in, const int* in_sizes, int n_in,
                              void* d_out, int out_size) {
    const float* x  = (const float*)d_in[0];
    const float* Ui = (const float*)d_in[1];
    const float* Vi = (const float*)d_in[2];
    const float* bi = (const float*)d_in[3];
    const float* Uf = (const float*)d_in[4];
    const float* Vf = (const float*)d_in[5];
    const float* bf = (const float*)d_in[6];
    const float* Uo = (const float*)d_in[7];
    const float* Vo = (const float*)d_in[8];
    const float* bo = (const float*)d_in[9];
    const float* Uc = (const float*)d_in[10];
    const float* Vc = (const float*)d_in[11];
    const float* bc = (const float*)d_in[12];
    float* out = (float*)d_out;

    static int smem_set = 0;
    if (!smem_set) {
        cudaFuncSetAttribute(lstm_rec, cudaFuncAttributeMaxDynamicSharedMemorySize,
                             SM_TOT * (int)sizeof(float));
        smem_set = 1;
    }

    dim3 ggrid(16, SEQ);
    xu_gemm<<<ggrid, 256>>>(x, Ui, Uf, Uo, Uc, bi, bf, bo, bc);

    int write_final = (out_size >= HS_ELEMS + 2 * BATCH * HID) ? 1 : 0;
    lstm_rec<<<NCTA, 256, SM_TOT * (int)sizeof(float)>>>(Vi, Vf, Vo, Vc, out, write_final);
}

// round 17
// speedup vs baseline: 1.5100x; 1.0506x over previous
#include <cuda_runtime.h>
#include <cuda_bf16.h>
#include <cstdint>

#define SEQ   2048
#define BATCH 64
#define HID   256
#define G4    1024
#define NCTA  128
#define HS_ELEMS (BATCH*SEQ*HID)

#define VT_LD  132
#define HS_LD  260
#define RED_LD 516
#define SM_VT  0
#define SM_H   (256*VT_LD)                    // 33792
#define SM_RED (SM_H + 4*HS_LD)               // 34832
#define SM_GA  (SM_RED + 2*8*RED_LD)          // 43088 : As[16][68]
#define SM_GB  (SM_GA + 16*68)                // 44176 : Bs[16][64]
#define SM_TOT (SM_GB + 16*64)                // 45200 floats = 180800 B

__device__ float              g_xU[(size_t)SEQ * BATCH * G4];
__device__ unsigned long long g_htag[2][BATCH * HID];   // {tag:u32, f32 bits}
__device__ unsigned           g_xcnt[SEQ];              // monotonic tile counters
__device__ unsigned           g_ticket;                 // launch epoch ticket

__device__ __forceinline__ unsigned long long ld_relaxed_u64(const unsigned long long* p) {
    unsigned long long v;
    asm volatile("ld.relaxed.gpu.global.u64 %0, [%1];" : "=l"(v) : "l"(p) : "memory");
    return v;
}
__device__ __forceinline__ void st_relaxed_u64(unsigned long long* p, unsigned long long v) {
    asm volatile("st.relaxed.gpu.global.u64 [%0], %1;" :: "l"(p), "l"(v) : "memory");
}
__device__ __forceinline__ unsigned ld_acquire_u32(const unsigned* p) {
    unsigned v;
    asm volatile("ld.acquire.gpu.global.u32 %0, [%1];" : "=r"(v) : "l"(p) : "memory");
    return v;
}
__device__ __forceinline__ void red_release_add(unsigned* p, unsigned v) {
    asm volatile("red.release.gpu.global.add.u32 [%0], %1;" :: "l"(p), "r"(v) : "memory");
}
__device__ __forceinline__ unsigned long long pack_ht(float h, unsigned tag) {
    return ((unsigned long long)tag << 32) | (unsigned long long)__float_as_uint(h);
}
__device__ __forceinline__ unsigned tag_of(unsigned long long v) { return (unsigned)(v >> 32); }
__device__ __forceinline__ float    val_of(unsigned long long v) { return __uint_as_float((unsigned)v); }

__device__ __forceinline__ void fma2(unsigned long long& d, unsigned long long a,
                                     unsigned long long b) {
    asm("fma.rn.f32x2 %0, %1, %2, %0;" : "+l"(d) : "l"(a), "l"(b));
}
__device__ __forceinline__ unsigned long long pack2(float x) {
    unsigned long long r;
    asm("mov.b64 %0, {%1, %1};" : "=l"(r) : "f"(x));
    return r;
}
__device__ __forceinline__ float2 unpack2(unsigned long long v) {
    float2 f;
    asm("mov.b64 {%0, %1}, %2;" : "=f"(f.x), "=f"(f.y) : "l"(v));
    return f;
}
__device__ __forceinline__ void bar_rec()  { asm volatile("bar.sync 1, 256;" ::: "memory"); }
__device__ __forceinline__ void bar_gemm() { asm volatile("bar.sync 2, 256;" ::: "memory"); }

__device__ __forceinline__ float sigf(float x)     { return 1.f / (1.f + __expf(-x)); }
__device__ __forceinline__ float tanhfast(float x) { return 1.f - 2.f / (__expf(2.f * x) + 1.f); }

// ---- fused kernel: 128 CTAs x 512 thr. warps 0-7 = recurrence, 8-15 = xU GEMM ----
__global__ void __launch_bounds__(512, 1) lstm_fused(
    const float* __restrict__ x,
    const float* __restrict__ U0, const float* __restrict__ U1,
    const float* __restrict__ U2, const float* __restrict__ U3,
    const float* __restrict__ B0, const float* __restrict__ B1,
    const float* __restrict__ B2, const float* __restrict__ B3,
    const float* __restrict__ V0, const float* __restrict__ V1,
    const float* __restrict__ V2, const float* __restrict__ V3,
    float* __restrict__ out, int write_final)
{
    extern __shared__ float sm[];
    float* vt  = sm + SM_VT;     // [256][VT_LD]
    float* h_s = sm + SM_H;      // [4][HS_LD]
    float* red = sm + SM_RED;    // [2][8][RED_LD]
    float* As  = sm + SM_GA;     // [16][68]
    float* Bs  = sm + SM_GB;     // [16][64]

    const int tid = threadIdx.x;
    const int ci  = blockIdx.x;

    // per-launch epoch (monotonic; makes all tags/counters replay-safe, no resets)
    __shared__ unsigned s_epoch;
    if (tid == 0) s_epoch = atomicAdd(&g_ticket, 1u) >> 7;   // /NCTA
    __syncthreads();              // the ONLY full-CTA barrier; roles diverge after
    const unsigned epoch = s_epoch;

    if (tid < 256) {
        // ================= RECURRENCE HALF (R16-proven) =================
        const int bg  = ci >> 3;
        const int cg  = ci & 7;
        const int b0  = bg * 4;
        const int u0  = cg * 32;

        for (int i = tid; i < 256 * 128; i += 256) {
            int k = i >> 7, c = i & 127;
            int g = c >> 5, uu = c & 31;
            const float* Vg = (g == 0) ? V0 : (g == 1) ? V1 : (g == 2) ? V2 : V3;
            vt[k * VT_LD + c] = Vg[k * 256 + u0 + uu];
        }
        bar_rec();

        const int ks    = tid >> 5;
        const int lane  = tid & 31;
        const int c0    = lane * 4;
        const int kbase = ks * 32;
        const int sb    = lane >> 3;
        const int skq   = (lane & 7) << 2;
        const int eb = tid >> 5;
        const int ul = tid & 31;
        float c_state = 0.f;

        const float* vbase = vt + kbase * VT_LD + c0;
        float* hstage = &h_s[sb * HS_LD + kbase + skq];
        const unsigned long long* hsrc0 = &g_htag[0][(b0 + sb) * 256 + kbase + skq];
        const unsigned long long* hsrc1 = &g_htag[1][(b0 + sb) * 256 + kbase + skq];
        unsigned long long* hdst = (tid < 128) ? &g_htag[0][(b0 + eb) * 256 + u0 + ul] : 0;
        const unsigned tagbase = epoch * (unsigned)SEQ;

        for (int t = 0; t < SEQ; ++t) {
            const int pr = t & 1, pw = pr ^ 1;

            // wait for xU[t] tiles (gemm half), then prefetch
            float xu0 = 0.f, xu1 = 0.f, xu2 = 0.f, xu3 = 0.f;
            if (tid < 128) {
                const unsigned xtarget = (epoch + 1u) * 16u;
                while (ld_acquire_u32(&g_xcnt[t]) < xtarget) {}
                const float* xp = g_xU + ((size_t)t * BATCH + b0 + eb) * G4 + u0 + ul;
                xu0 = __ldg(xp); xu1 = __ldg(xp + 256);
                xu2 = __ldg(xp + 512); xu3 = __ldg(xp + 768);
            }

            // tagged h poll + stage
            if (t == 0) {
                *(float4*)hstage = make_float4(0.f, 0.f, 0.f, 0.f);
            } else {
                const unsigned long long* hp = pr ? hsrc1 : hsrc0;
                unsigned long long v0, v1, v2, v3;
                const unsigned wanted = tagbase + (unsigned)t;
                do {
                    v0 = ld_relaxed_u64(hp + 0);
                    v1 = ld_relaxed_u64(hp + 1);
                    v2 = ld_relaxed_u64(hp + 2);
                    v3 = ld_relaxed_u64(hp + 3);
                } while (tag_of(v0) < wanted || tag_of(v1) < wanted ||
                         tag_of(v2) < wanted || tag_of(v3) < wanted);
                *(float4*)hstage = make_float4(val_of(v0), val_of(v1), val_of(v2), val_of(v3));
            }
            __syncwarp();

            float acc[4][4] = {};
#pragma unroll
            for (int kk = 0; kk < 32; kk += 4) {
                float4 h0v = *(const float4*)&h_s[0 * HS_LD + kbase + kk];
                float4 h1v = *(const float4*)&h_s[1 * HS_LD + kbase + kk];
                float4 h2v = *(const float4*)&h_s[2 * HS_LD + kbase + kk];
                float4 h3v = *(const float4*)&h_s[3 * HS_LD + kbase + kk];
                const float* vp = vbase + kk * VT_LD;
                float4 va = *(const float4*)(vp);
                float4 vb = *(const float4*)(vp + VT_LD);
                float4 vc = *(const float4*)(vp + 2 * VT_LD);
                float4 vd = *(const float4*)(vp + 3 * VT_LD);
#define MAC4(hb, b) \
                acc[b][0] += hb.x*va.x + hb.y*vb.x + hb.z*vc.x + hb.w*vd.x; \
                acc[b][1] += hb.x*va.y + hb.y*vb.y + hb.z*vc.y + hb.w*vd.y; \
                acc[b][2] += hb.x*va.z + hb.y*vb.z + hb.z*vc.z + hb.w*vd.z; \
                acc[b][3] += hb.x*va.w + hb.y*vb.w + hb.z*vc.w + hb.w*vd.w;
                MAC4(h0v, 0) MAC4(h1v, 1) MAC4(h2v, 2) MAC4(h3v, 3)
#undef MAC4
            }

            {
                float* rp = red + (pr * 8 + ks) * RED_LD + c0;
                *(float4*)&rp[0 * 128] = make_float4(acc[0][0], acc[0][1], acc[0][2], acc[0][3]);
                *(float4*)&rp[1 * 128] = make_float4(acc[1][0], acc[1][1], acc[1][2], acc[1][3]);
                *(float4*)&rp[2 * 128] = make_float4(acc[2][0], acc[2][1], acc[2][2], acc[2][3]);
                *(float4*)&rp[3 * 128] = make_float4(acc[3][0], acc[3][1], acc[3][2], acc[3][3]);
            }
            bar_rec();   // the only per-step rec barrier

            if (tid < 128) {
                float z0 = xu0, z1 = xu1, z2 = xu2, z3 = xu3;
                int base = eb * 128 + ul;
                const float* rpar = red + pr * 8 * RED_LD;
#pragma unroll
                for (int s = 0; s < 8; ++s) {
                    const float* rr = rpar + s * RED_LD + base;
                    z0 += rr[0]; z1 += rr[32]; z2 += rr[64]; z3 += rr[96];
                }
                float ig = sigf(z0), fg = sigf(z1), og = sigf(z2), gg = tanhfast(z3);
                c_state = fg * c_state + ig * gg;
                float h = og * tanhfast(c_state);

                st_relaxed_u64(hdst + (size_t)pw * BATCH * HID,
                               pack_ht(h, tagbase + (unsigned)(t + 1)));

                int b = b0 + eb, u = u0 + ul;
                out[((size_t)b * SEQ + t) * HID + u] = h;
                if (write_final && t == SEQ - 1) {
                    out[(size_t)HS_ELEMS + b * HID + u]               = h;
                    out[(size_t)HS_ELEMS + BATCH * HID + b * HID + u] = c_state;
                }
            }
        }
    } else {
        // ================= GEMM HALF: 256 jobs/CTA, t-ascending =================
        const int gt   = tid - 256;
        const int ty   = gt >> 4;
        const int tx   = gt & 15;
        const int bRow = gt >> 2;
        const int kq   = (gt & 3) << 2;
        const int kRow = gt >> 4;
        const int n4   = (gt & 15) << 2;

        for (int jj = 0; jj < 256; ++jj) {
            const int j    = jj * NCTA + ci;
            const int t    = j >> 4;
            const int nb   = j & 15;
            const int gate  = nb >> 2;
            const int ucol0 = (nb & 3) * 64;
            const float* U  = (gate == 0) ? U0 : (gate == 1) ? U1 : (gate == 2) ? U2 : U3;
            const float* Bb = (gate == 0) ? B0 : (gate == 1) ? B1 : (gate == 2) ? B2 : B3;

            const float* xrow = x + ((size_t)bRow * SEQ + t) * 256;
            unsigned long long acc2[4][2] = {};

            for (int kb = 0; kb < 256; kb += 16) {
                float4 xa = *(const float4*)(xrow + kb + kq);
                As[(kq + 0) * 68 + bRow] = xa.x;
                As[(kq + 1) * 68 + bRow] = xa.y;
                As[(kq + 2) * 68 + bRow] = xa.z;
                As[(kq + 3) * 68 + bRow] = xa.w;
                *(float4*)&Bs[kRow * 64 + n4] =
                    *(const float4*)(U + (size_t)(kb + kRow) * 256 + ucol0 + n4);
                bar_gemm();
#pragma unroll
                for (int kk = 0; kk < 16; ++kk) {
                    float4 a = *(float4*)&As[kk * 68 + ty * 4];
                    ulonglong2 bp = *(const ulonglong2*)&Bs[kk * 64 + tx * 4];
                    unsigned long long a0 = pack2(a.x), a1 = pack2(a.y),
                                       a2 = pack2(a.z), a3 = pack2(a.w);
                    fma2(acc2[0][0], a0, bp.x); fma2(acc2[0][1], a0, bp.y);
                    fma2(acc2[1][0], a1, bp.x); fma2(acc2[1][1], a1, bp.y);
                    fma2(acc2[2][0], a2, bp.x); fma2(acc2[2][1], a2, bp.y);
                    fma2(acc2[3][0], a3, bp.x); fma2(acc2[3][1], a3, bp.y);
                }
                bar_gemm();
            }

            float4 bv4 = *(const float4*)(Bb + ucol0 + tx * 4);
#pragma unroll
            for (int i = 0; i < 4; ++i) {
                int row = t * BATCH + ty * 4 + i;
                float2 lo = unpack2(acc2[i][0]), hi = unpack2(acc2[i][1]);
                float4 o;
                o.x = lo.x + bv4.x;
                o.y = lo.y + bv4.y;
                o.z = hi.x + bv4.z;
                o.w = hi.y + bv4.w;
                *(float4*)&g_xU[(size_t)row * G4 + nb * 64 + tx * 4] = o;
            }
            bar_gemm();                              // tile stores happen-before release
            if (gt == 0) red_release_add(&g_xcnt[t], 1u);
        }
    }
}

extern "C" void kernel_launch(void* const* d_in, const int* in_sizes, int n_in,
                              void* d_out, int out_size) {
    const float* x  = (const float*)d_in[0];
    const float* Ui = (const float*)d_in[1];
    const float* Vi = (const float*)d_in[2];
    const float* bi = (const float*)d_in[3];
    const float* Uf = (const float*)d_in[4];
    const float* Vf = (const float*)d_in[5];
    const float* bf = (const float*)d_in[6];
    const float* Uo = (const float*)d_in[7];
    const float* Vo = (const float*)d_in[8];
    const float* bo = (const float*)d_in[9];
    const float* Uc = (const float*)d_in[10];
    const float* Vc = (const float*)d_in[11];
    const float* bc = (const float*)d_in[12];
    float* out = (float*)d_out;

    static int smem_set = 0;
    if (!smem_set) {
        cudaFuncSetAttribute(lstm_fused, cudaFuncAttributeMaxDynamicSharedMemorySize,
                             SM_TOT * (int)sizeof(float));
        smem_set = 1;
    }

    int write_final = (out_size >= HS_ELEMS + 2 * BATCH * HID) ? 1 : 0;
    lstm_fused<<<NCTA, 512, SM_TOT * (int)sizeof(float)>>>(
        x, Ui, Uf, Uo, Uc, bi, bf, bo, bc, Vi, Vf, Vo, Vc, out, write_final);
}